// round 1
// baseline (speedup 1.0000x reference)
#include <cuda_runtime.h>

#define NXc 64
#define NYc 64
#define NSPOTS 64
#define PATCH_HW 3
#define Pc 6
#define TPB 256

// z layout: row b = [x0[0..63], y0[0..63]]  (B, 2*NSPOTS)
__global__ __launch_bounds__(TPB) void spot_render_kernel(
    const float* __restrict__ z, float* __restrict__ out)
{
    __shared__ float img[NXc * NYc];          // 16 KB accumulation image
    __shared__ float slx[NSPOTS][Pc];         // I0 * lambda_x, zeroed if invalid
    __shared__ float sly[NSPOTS][Pc];         // lambda_y
    __shared__ int   spx[NSPOTS];
    __shared__ int   spy[NSPOTS];

    const int b   = blockIdx.x;
    const int tid = threadIdx.x;

    // zero the shared image
    #pragma unroll
    for (int i = tid; i < NXc * NYc; i += TPB) img[i] = 0.0f;

    const float inv_alpha = 1.0f / (1.41421356237f * 0.92f);  // 1/(sqrt(2)*sigma)
    const float I0 = 1000.0f;

    // Phase 1: 64 spots * 12 lambda values = 768 work items
    const float* zrow = z + (size_t)b * (2 * NSPOTS);
    for (int i = tid; i < NSPOTS * 2 * Pc; i += TPB) {
        const int s = i / (2 * Pc);
        const int j = i - s * (2 * Pc);      // 0..11
        const float x0 = zrow[s];
        const float y0 = zrow[NSPOTS + s];
        const int px = __float2int_rn(x0) - PATCH_HW;   // round-half-even, matches jnp.round
        const int py = __float2int_rn(y0) - PATCH_HW;
        const bool valid = (px >= 0) & (px < NXc - Pc) & (py >= 0) & (py < NYc - Pc);

        float t0, t;
        if (j < Pc) { t0 = x0 - (float)px; t = (float)j; }
        else        { t0 = y0 - (float)py; t = (float)(j - Pc); }

        float lam = 0.5f * (erff((t + 0.5f - t0) * inv_alpha) -
                            erff((t - 0.5f - t0) * inv_alpha));
        if (j < Pc) lam *= I0;
        if (!valid) lam = 0.0f;

        if (j < Pc) slx[s][j] = lam;
        else        sly[s][j - Pc] = lam;

        if (j == 0) {
            spx[s] = valid ? px : 0;
            spy[s] = valid ? py : 0;
        }
    }
    __syncthreads();

    // Phase 2: scatter 64 spots * 36 pixels = 2304 updates into shared image
    for (int i = tid; i < NSPOTS * Pc * Pc; i += TPB) {
        const int s  = i / (Pc * Pc);
        const int p  = i - s * (Pc * Pc);
        const int ix = p / Pc;
        const int iy = p - ix * Pc;
        const float v = slx[s][ix] * sly[s][iy];
        const int row = spx[s] + ix;   // px -> row (flat = row*NY + col)
        const int col = spy[s] + iy;
        atomicAdd(&img[row * NYc + col], v);
    }
    __syncthreads();

    // Phase 3: coalesced float4 writeback
    float4* o  = reinterpret_cast<float4*>(out + (size_t)b * (NXc * NYc));
    const float4* im = reinterpret_cast<const float4*>(img);
    #pragma unroll
    for (int i = tid; i < (NXc * NYc) / 4; i += TPB) o[i] = im[i];
}

extern "C" void kernel_launch(void* const* d_in, const int* in_sizes, int n_in,
                              void* d_out, int out_size)
{
    const float* z = (const float*)d_in[0];
    float* out = (float*)d_out;
    const int B = in_sizes[0] / (2 * NSPOTS);   // 8192
    spot_render_kernel<<<B, TPB>>>(z, out);
}